// round 7
// baseline (speedup 1.0000x reference)
#include <cuda_runtime.h>
#include <math.h>
#include <stdint.h>

#define BSZ 1024
#define NN  100
#define HH  128
#define MTOT (BSZ * NN)   // 102400

// ---------------- scratch (no allocs allowed) ----------------
__device__ float g_h0[(size_t)MTOT * HH];
__device__ float g_e[(size_t)MTOT * 2 * HH];
__device__ float g_inp[(size_t)MTOT * 2 * HH];
__device__ float g_gi[(size_t)MTOT * 3 * HH];
__device__ float g_gh[(size_t)MTOT * 3 * HH];
__device__ float g_hid[(size_t)MTOT * HH];
__device__ float g_star[(size_t)BSZ * HH];
// tf32-rounded weight copies
__device__ float g_wih[3 * HH * 2 * HH];
__device__ float g_whh[3 * HH * HH];
__device__ float g_wein[HH * HH];
__device__ float g_weout[HH * HH];
__device__ float g_whn[HH * 2 * HH];

// ---------------- helpers ----------------
__device__ __forceinline__ float totf(float x) {
    uint32_t u; asm("cvt.rna.tf32.f32 %0, %1;" : "=r"(u) : "f"(x));
    return __uint_as_float(u);
}
__device__ __forceinline__ float sigm(float x) { return 1.f / (1.f + expf(-x)); }

__device__ __forceinline__ void mma8(float c[4], float2 a01, float2 a23, float2 b01) {
    asm volatile(
        "mma.sync.aligned.m16n8k8.row.col.f32.tf32.tf32.f32 "
        "{%0,%1,%2,%3},{%4,%5,%6,%7},{%8,%9},{%0,%1,%2,%3};"
        : "+f"(c[0]), "+f"(c[1]), "+f"(c[2]), "+f"(c[3])
        : "r"(__float_as_uint(a01.x)), "r"(__float_as_uint(a01.y)),
          "r"(__float_as_uint(a23.x)), "r"(__float_as_uint(a23.y)),
          "r"(__float_as_uint(b01.x)), "r"(__float_as_uint(b01.y)));
}

// =======================================================================
// Fat-warp tf32 GEMM: 128 threads, CTA tile 128x128, warp tile 64x64,
// BK=16 double-buffered, 1 barrier per K-step. Inputs must be pre-rounded
// to tf32 (HW RZ truncation then exact).
// C[m, bx*128 + n] = sum_k Asel[m,k] * B[(lb*128+n), k] + bias
// B/bias picked per bx: bx < bx_split -> B1 else B2 (lb = bx - split).
// SPLITK: A = A1 for k < ksplit else A2 (k-ksplit); both lda.
// EPI 0: store; EPI 1: a = sigm(v); C = a*ep1 + (1-a)*ep2 (both ld HH)
// =======================================================================
template<int EPI, bool SPLITK>
__global__ __launch_bounds__(128, 2)
void tcb_gemm(const float* __restrict__ A1, const float* __restrict__ A2,
              int lda, int ksplit,
              const float* __restrict__ B1, const float* __restrict__ B2, int bx_split,
              const float* __restrict__ bias1, const float* __restrict__ bias2,
              const float* __restrict__ ep1, const float* __restrict__ ep2,
              float* __restrict__ C, int ldc, int K)
{
    __shared__ float2 As2[2][16][68];    // {A[m][k], A[m+8][k]} pairs
    __shared__ float2 Bs2[2][8][132];    // {B[n][k8], B[n][k8+4]} pairs

    const int tid = threadIdx.x;
    const int lane = tid & 31, warp = tid >> 5;
    const int wm = warp >> 1, wn = warp & 1;
    const int g = lane >> 2, tig = lane & 3;
    const int m0 = blockIdx.y * 128;
    const int bx = blockIdx.x;

    const int lb = (bx < bx_split) ? bx : bx - bx_split;
    const float* Brow = ((bx < bx_split) ? B1 : B2) + (long)(lb * 128 + tid) * K;
    const float* biasp = ((bx < bx_split) ? bias1 : bias2) + lb * 128;

    const float* Arow1 = A1 + (long)(m0 + tid) * lda;
    const float* Arow2 = SPLITK ? (A2 + (long)(m0 + tid) * lda) : Arow1;

    const int a_idx  = ((tid >> 4) << 3) + (tid & 7);
    const int a_half = (tid >> 3) & 1;

    float acc[4][8][4] = {};
    __align__(16) float va[16];
    __align__(16) float vb[16];
    const int T = K >> 4;

    auto ldg = [&](int k0) {
        const float* ap;
        if (SPLITK) ap = (k0 < ksplit) ? (Arow1 + k0) : (Arow2 + (k0 - ksplit));
        else        ap = Arow1 + k0;
        #pragma unroll
        for (int q = 0; q < 4; q++)
            *reinterpret_cast<float4*>(va + 4 * q) =
                *reinterpret_cast<const float4*>(ap + 4 * q);
        #pragma unroll
        for (int q = 0; q < 4; q++)
            *reinterpret_cast<float4*>(vb + 4 * q) =
                *reinterpret_cast<const float4*>(Brow + k0 + 4 * q);
    };

    auto sts = [&](int s) {
        #pragma unroll
        for (int j = 0; j < 16; j++) {
            float* d = &As2[s][j][a_idx].x;
            d[a_half] = va[j];
        }
        #pragma unroll
        for (int j = 0; j < 16; j++) {
            float* d = &Bs2[s][((j >> 3) << 2) + (j & 3)][tid].x;
            d[(j >> 2) & 1] = vb[j];
        }
    };

    auto comp = [&](int s) {
        #pragma unroll
        for (int ks = 0; ks < 2; ks++) {
            float2 a01[4], a23[4], bb[8];
            #pragma unroll
            for (int mt = 0; mt < 4; mt++) {
                int idx = (wm * 4 + mt) * 8 + g;
                a01[mt] = As2[s][ks * 8 + tig][idx];
                a23[mt] = As2[s][ks * 8 + tig + 4][idx];
            }
            #pragma unroll
            for (int nt = 0; nt < 8; nt++)
                bb[nt] = Bs2[s][ks * 4 + tig][wn * 64 + nt * 8 + g];
            #pragma unroll
            for (int mt = 0; mt < 4; mt++)
                #pragma unroll
                for (int nt = 0; nt < 8; nt++)
                    mma8(acc[mt][nt], a01[mt], a23[mt], bb[nt]);
        }
    };

    ldg(0); sts(0); __syncthreads();
    for (int t = 0; t < T; t++) {
        if (t + 1 < T) ldg((t + 1) << 4);
        comp(t & 1);
        if (t + 1 < T) { sts((t + 1) & 1); __syncthreads(); }
    }

    // epilogue
    #pragma unroll
    for (int mt = 0; mt < 4; mt++) {
        #pragma unroll
        for (int half = 0; half < 2; half++) {
            int m = m0 + wm * 64 + mt * 16 + g + half * 8;
            #pragma unroll
            for (int nt = 0; nt < 8; nt++) {
                int nl = wn * 64 + nt * 8 + tig * 2;
                float v0 = acc[mt][nt][half * 2 + 0] + biasp[nl];
                float v1 = acc[mt][nt][half * 2 + 1] + biasp[nl + 1];
                float2* cp = reinterpret_cast<float2*>(C + (long)m * ldc + bx * 128 + nl);
                if (EPI == 1) {
                    float2 hv = *reinterpret_cast<const float2*>(ep1 + (long)m * HH + nl);
                    float2 dv = *reinterpret_cast<const float2*>(ep2 + (long)m * HH + nl);
                    float a0 = sigm(v0), a1 = sigm(v1);
                    *cp = make_float2(a0 * hv.x + (1.f - a0) * dv.x,
                                      a1 * hv.y + (1.f - a1) * dv.y);
                } else {
                    *cp = make_float2(v0, v1);
                }
            }
        }
    }
}

// ================= adjacency GEMM (round-4 proven; rounds its output) =====
template<bool BT, bool GUARD>
__global__ __launch_bounds__(256, 2)
void tc_gemm(const float* __restrict__ A1, long sA, int lda,
             const float* __restrict__ B1, long sB, int ldb,
             const float* __restrict__ bias1,
             float* __restrict__ C, long sC, int ldc,
             int M, int N, int K)
{
    __shared__ float2 As2[2][16][68];
    __shared__ float2 Bs2[2][8][132];

    A1 += (long)blockIdx.z * sA;
    C  += (long)blockIdx.z * sC;
    const int m0 = blockIdx.y * 128, n0 = blockIdx.x * 128;
    const int tid = threadIdx.x;
    const int lane = tid & 31, warp = tid >> 5;
    const int wm = warp >> 1, wn = warp & 1;
    const int g = lane >> 2, tig = lane & 3;

    const int a_row = tid >> 1, a_kg = (tid & 1) << 3;
    const float* pA1 = A1 + (long)(m0 + a_row) * lda + a_kg;
    const int a_idx  = ((a_row >> 4) << 3) + (a_row & 7);
    const int a_half = (a_row >> 3) & 1;

    const float* Bp;
    int b_kg = 0, b_k = 0, b_n8 = 0;
    if (BT) {
        int b_n = tid >> 1; b_kg = (tid & 1) << 3;
        Bp = B1 + (long)(n0 + b_n) * ldb + b_kg;
    } else {
        b_k = tid >> 4;
        b_n8 = (tid & 15) << 3;
        Bp = B1 + (long)blockIdx.z * sB + (long)b_k * ldb + n0 + b_n8;
    }

    float acc[2][8][4] = {};
    __align__(16) float va[8];
    __align__(16) float vb[8];
    const int T = (K + 15) >> 4;

    auto ldg = [&](int k0) {
        if (!GUARD) {
            *reinterpret_cast<float4*>(va)     = *reinterpret_cast<const float4*>(pA1 + k0);
            *reinterpret_cast<float4*>(va + 4) = *reinterpret_cast<const float4*>(pA1 + k0 + 4);
        } else {
            bool rok = (m0 + a_row) < M;
            if (rok && (k0 + a_kg + 8) <= K) {
                *reinterpret_cast<float4*>(va)     = *reinterpret_cast<const float4*>(pA1 + k0);
                *reinterpret_cast<float4*>(va + 4) = *reinterpret_cast<const float4*>(pA1 + k0 + 4);
            } else {
                #pragma unroll
                for (int j = 0; j < 8; j++)
                    va[j] = (rok && (k0 + a_kg + j) < K) ? pA1[k0 + j] : 0.f;
            }
        }
        if (BT) {
            *reinterpret_cast<float4*>(vb)     = *reinterpret_cast<const float4*>(Bp + k0);
            *reinterpret_cast<float4*>(vb + 4) = *reinterpret_cast<const float4*>(Bp + k0 + 4);
        } else {
            if ((k0 + b_k) < K) {
                const float* bp = Bp + (long)k0 * ldb;
                *reinterpret_cast<float4*>(vb)     = *reinterpret_cast<const float4*>(bp);
                *reinterpret_cast<float4*>(vb + 4) = *reinterpret_cast<const float4*>(bp + 4);
            } else {
                #pragma unroll
                for (int j = 0; j < 8; j++) vb[j] = 0.f;
            }
        }
    };

    auto sts = [&](int s) {
        #pragma unroll
        for (int j = 0; j < 8; j++) {
            float* d = &As2[s][a_kg + j][a_idx].x;
            d[a_half] = totf(va[j]);
        }
        if (BT) {
            #pragma unroll
            for (int j = 0; j < 8; j++) {
                int k = b_kg + j;
                float* d = &Bs2[s][((k >> 3) << 2) + (k & 3)][tid >> 1].x;
                d[(k >> 2) & 1] = totf(vb[j]);
            }
        } else {
            int k = b_k;
            float* drow = &Bs2[s][((k >> 3) << 2) + (k & 3)][b_n8].x;
            int h = (k >> 2) & 1;
            #pragma unroll
            for (int j = 0; j < 8; j++) drow[j * 2 + h] = totf(vb[j]);
        }
    };

    auto comp = [&](int s) {
        #pragma unroll
        for (int ks = 0; ks < 2; ks++) {
            float2 a01[2], a23[2], bb[8];
            #pragma unroll
            for (int mt = 0; mt < 2; mt++) {
                int idx = (wm * 2 + mt) * 8 + g;
                a01[mt] = As2[s][ks * 8 + tig][idx];
                a23[mt] = As2[s][ks * 8 + tig + 4][idx];
            }
            #pragma unroll
            for (int nt = 0; nt < 8; nt++)
                bb[nt] = Bs2[s][ks * 4 + tig][wn * 64 + nt * 8 + g];
            #pragma unroll
            for (int mt = 0; mt < 2; mt++)
                #pragma unroll
                for (int nt = 0; nt < 8; nt++)
                    mma8(acc[mt][nt], a01[mt], a23[mt], bb[nt]);
        }
    };

    ldg(0); sts(0); __syncthreads();
    for (int t = 0; t < T; t++) {
        if (t + 1 < T) ldg((t + 1) << 4);
        comp(t & 1);
        if (t + 1 < T) { sts((t + 1) & 1); __syncthreads(); }
    }

    #pragma unroll
    for (int mt = 0; mt < 2; mt++) {
        int mrow = m0 + wm * 32 + mt * 16 + g;
        #pragma unroll
        for (int half = 0; half < 2; half++) {
            int m = mrow + half * 8;
            if (GUARD && m >= M) continue;
            #pragma unroll
            for (int nt = 0; nt < 8; nt++) {
                int n = n0 + wn * 64 + nt * 8 + tig * 2;
                float v0 = acc[mt][nt][half * 2 + 0] + bias1[n];
                float v1 = acc[mt][nt][half * 2 + 1] + bias1[n + 1];
                *reinterpret_cast<float2*>(C + (long)m * ldc + n) =
                    make_float2(totf(v0), totf(v1));
            }
        }
    }
}

// ---------------- elementwise / small kernels ----------------
__global__ void round_copy_k(const float4* __restrict__ src, float4* __restrict__ dst, int n4)
{
    int i = blockIdx.x * blockDim.x + threadIdx.x;
    if (i >= n4) return;
    float4 v = src[i];
    dst[i] = make_float4(totf(v.x), totf(v.y), totf(v.z), totf(v.w));
}

__global__ void gather_k(const int* __restrict__ inputs,
                         const float4* __restrict__ emb4,
                         float4* __restrict__ h04, long total4)
{
    long i = (long)blockIdx.x * blockDim.x + threadIdx.x;
    if (i >= total4) return;
    long m = i >> 5;
    int  t = (int)(i & 31);
    float4 v = emb4[(long)inputs[m] * 32 + t];
    h04[i] = make_float4(totf(v.x), totf(v.y), totf(v.z), totf(v.w));
}

__global__ void pool_k(const float* __restrict__ h0,
                       const int* __restrict__ gm,
                       float* __restrict__ star)
{
    int b = blockIdx.x, t = threadIdx.x;
    float s = 0.f, c = 0.f;
    const float* hb = h0 + (long)b * NN * HH;
    const int* gb = gm + b * NN;
    for (int i = 0; i < NN; i++) {
        float gmask = (float)gb[i];
        s += gmask * hb[(long)i * HH + t];
        c += gmask;
    }
    star[b * HH + t] = s / c;
}

// fused GRU + star blend + attention pooling; writes hid (tf32-rounded)
// and the final star directly into out_star.
__global__ void star_gru_k(const float* __restrict__ gi, const float* __restrict__ gh,
                           const float* __restrict__ h0, const int* __restrict__ gm,
                           const float* __restrict__ star_in,
                           float* __restrict__ hid, float* __restrict__ star_out)
{
    const float inv_sqrt_h = 0.0883883476483184f;  // 1/sqrt(128)
    int b = blockIdx.x;
    int t = threadIdx.x;
    int lane = t & 31, warp = t >> 5;

    __shared__ float st[HH];
    __shared__ float w[NN];
    __shared__ float red[HH];

    st[t] = star_in[(long)b * HH + t];
    __syncthreads();

    float ssp = 0.f;
    #pragma unroll
    for (int u = 0; u < 4; u++) { float v = st[lane + 32 * u]; ssp += v * v; }
    #pragma unroll
    for (int off = 16; off > 0; off >>= 1) ssp += __shfl_xor_sync(0xffffffffu, ssp, off);
    float ss = ssp;

    float* hb = hid + (long)b * NN * HH;

    for (int i = warp; i < NN; i += 4) {
        long row = (long)b * NN + i;
        const float* gir = gi + row * (3 * HH);
        const float* ghr = gh + row * (3 * HH);
        const float* h0r = h0 + row * HH;
        float hv[4];
        float d = 0.f;
        #pragma unroll
        for (int u = 0; u < 4; u++) {
            int c = lane + 32 * u;
            float r  = sigm(gir[c] + ghr[c]);
            float ig = sigm(gir[c + HH] + ghr[c + HH]);
            float ng = tanhf(gir[c + 2 * HH] + r * ghr[c + 2 * HH]);
            float h  = h0r[c];
            hv[u] = ng + ig * (h - ng);
            d += hv[u] * st[c];
        }
        #pragma unroll
        for (int off = 16; off > 0; off >>= 1) d += __shfl_xor_sync(0xffffffffu, d, off);
        float alpha = sigm(d * inv_sqrt_h);
        float* hr = hb + (long)i * HH;
        #pragma unroll
        for (int u = 0; u < 4; u++) {
            int c = lane + 32 * u;
            hr[c] = totf((1.f - alpha) * hv[u] + alpha * st[c]);
        }
        float d2 = (1.f - alpha) * d + alpha * ss;
        if (lane == 0) w[i] = expf(d2) * (float)gm[b * NN + i];
    }
    __syncthreads();

    red[t] = (t < NN) ? w[t] : 0.f;
    __syncthreads();
    for (int s = 64; s > 0; s >>= 1) {
        if (t < s) red[t] += red[t + s];
        __syncthreads();
    }
    float S = red[0] + 1e-24f;

    float acc = 0.f;
    for (int i = 0; i < NN; i++) acc += w[i] * hb[(long)i * HH + t];
    star_out[(long)b * HH + t] = acc / S;
}

// ---------------- launch ----------------
extern "C" void kernel_launch(void* const* d_in, const int* in_sizes, int n_in,
                              void* d_out, int out_size)
{
    const int*   inputs = (const int*)d_in[0];
    const float* A      = (const float*)d_in[1];
    const int*   gm     = (const int*)d_in[2];
    const float* emb    = (const float*)d_in[3];
    const float* w_ih   = (const float*)d_in[4];
    const float* w_hh   = (const float*)d_in[5];
    const float* b_ih   = (const float*)d_in[6];
    const float* b_hh   = (const float*)d_in[7];
    const float* b_iah  = (const float*)d_in[8];
    const float* b_oah  = (const float*)d_in[9];
    const float* W_ein  = (const float*)d_in[10];
    const float* b_ein  = (const float*)d_in[11];
    const float* W_eout = (const float*)d_in[12];
    const float* b_eout = (const float*)d_in[13];
    const float* W_hn   = (const float*)d_in[14];
    const float* b_hn   = (const float*)d_in[15];
    float* out = (float*)d_out;

    float *h0, *e, *inp, *gi, *gh, *hid, *star;
    float *wih, *whh, *wein, *weout, *whn;
    cudaGetSymbolAddress((void**)&h0,    g_h0);
    cudaGetSymbolAddress((void**)&e,     g_e);
    cudaGetSymbolAddress((void**)&inp,   g_inp);
    cudaGetSymbolAddress((void**)&gi,    g_gi);
    cudaGetSymbolAddress((void**)&gh,    g_gh);
    cudaGetSymbolAddress((void**)&hid,   g_hid);
    cudaGetSymbolAddress((void**)&star,  g_star);
    cudaGetSymbolAddress((void**)&wih,   g_wih);
    cudaGetSymbolAddress((void**)&whh,   g_whh);
    cudaGetSymbolAddress((void**)&wein,  g_wein);
    cudaGetSymbolAddress((void**)&weout, g_weout);
    cudaGetSymbolAddress((void**)&whn,   g_whn);

    const long totBNH = (long)MTOT * HH;
    const int BIG = 1 << 30;

    // 0) round weights (tf32-rna) so mma.sync RZ truncation is exact
    round_copy_k<<<(3*HH*2*HH/4 + 255)/256, 256>>>((const float4*)w_ih,  (float4*)wih,  3*HH*2*HH/4);
    round_copy_k<<<(3*HH*HH/4   + 255)/256, 256>>>((const float4*)w_hh,  (float4*)whh,  3*HH*HH/4);
    round_copy_k<<<(HH*HH/4     + 255)/256, 256>>>((const float4*)W_ein, (float4*)wein, HH*HH/4);
    round_copy_k<<<(HH*HH/4     + 255)/256, 256>>>((const float4*)W_eout,(float4*)weout,HH*HH/4);
    round_copy_k<<<(HH*2*HH/4   + 255)/256, 256>>>((const float4*)W_hn,  (float4*)whn,  HH*2*HH/4);

    // 1) gather (rounded) + initial star
    gather_k<<<(unsigned)((totBNH / 4 + 255) / 256), 256>>>(
        inputs, (const float4*)emb, (float4*)h0, totBNH / 4);
    pool_k<<<BSZ, HH>>>(h0, gm, star);

    // 2) e = [h0 @ W_ein^T + b_ein | h0 @ W_eout^T + b_eout]
    tcb_gemm<0, false><<<dim3(2, MTOT / 128), 128>>>(
        h0, h0, HH, 0,
        wein, weout, 1,
        b_ein, b_eout,
        nullptr, nullptr,
        e, 2 * HH, HH);

    // 3) batched adjacency GEMMs (M=100, N=128, K=100; rounds outputs)
    tc_gemm<false, true><<<dim3(1, 1, BSZ), 256>>>(
        A, (long)NN * 2 * NN, 2 * NN,
        e, (long)NN * 2 * HH, 2 * HH,
        b_iah,
        inp, (long)NN * 2 * HH, 2 * HH,
        NN, HH, NN);
    tc_gemm<false, true><<<dim3(1, 1, BSZ), 256>>>(
        A + NN, (long)NN * 2 * NN, 2 * NN,
        e + HH, (long)NN * 2 * HH, 2 * HH,
        b_oah,
        inp + HH, (long)NN * 2 * HH, 2 * HH,
        NN, HH, NN);

    // 4) gi = inp @ w_ih^T + b_ih ; gh = h0 @ w_hh^T + b_hh
    tcb_gemm<0, false><<<dim3(3, MTOT / 128), 128>>>(
        inp, inp, 2 * HH, 0,
        wih, wih, BIG,
        b_ih, b_ih,
        nullptr, nullptr,
        gi, 3 * HH, 2 * HH);
    tcb_gemm<0, false><<<dim3(3, MTOT / 128), 128>>>(
        h0, h0, HH, 0,
        whh, whh, BIG,
        b_hh, b_hh,
        nullptr, nullptr,
        gh, 3 * HH, HH);

    // 5+6) fused GRU + star blend + attention pooling (writes hid, star->out)
    star_gru_k<<<BSZ, HH>>>(gi, gh, h0, gm, star, hid, out + totBNH);

    // 7+8) highway fused: logits = [h0|hid] @ W_hn^T + b_hn, sigmoid blend -> out
    tcb_gemm<1, true><<<dim3(1, MTOT / 128), 128>>>(
        h0, hid, HH, HH,
        whn, whn, BIG,
        b_hn, b_hn,
        h0, hid,
        out, HH, 2 * HH);
}

// round 8
// speedup vs baseline: 1.1012x; 1.1012x over previous
#include <cuda_runtime.h>
#include <math.h>
#include <stdint.h>

#define BSZ 1024
#define NN  100
#define HH  128
#define MTOT (BSZ * NN)   // 102400

// ---------------- scratch (no allocs allowed) ----------------
__device__ float g_h0[(size_t)MTOT * HH];
__device__ float g_e[(size_t)MTOT * 2 * HH];
__device__ float g_inp[(size_t)MTOT * 2 * HH];
__device__ float g_gi[(size_t)MTOT * 3 * HH];
__device__ float g_gh[(size_t)MTOT * 3 * HH];
__device__ float g_hid[(size_t)MTOT * HH];
__device__ float g_star[(size_t)BSZ * HH];
// tf32-rounded weight copies (contiguous block for one-shot rounding)
__device__ float g_wih[3 * HH * 2 * HH];   // 98304
__device__ float g_whh[3 * HH * HH];       // 49152
__device__ float g_wein[HH * HH];          // 16384
__device__ float g_weout[HH * HH];         // 16384
__device__ float g_whn[HH * 2 * HH];       // 32768

// ---------------- helpers ----------------
__device__ __forceinline__ float totf(float x) {
    uint32_t u; asm("cvt.rna.tf32.f32 %0, %1;" : "=r"(u) : "f"(x));
    return __uint_as_float(u);
}
__device__ __forceinline__ float sigm(float x) { return 1.f / (1.f + expf(-x)); }

__device__ __forceinline__ void mma8(float c[4], float2 a01, float2 a23, float2 b01) {
    asm volatile(
        "mma.sync.aligned.m16n8k8.row.col.f32.tf32.tf32.f32 "
        "{%0,%1,%2,%3},{%4,%5,%6,%7},{%8,%9},{%0,%1,%2,%3};"
        : "+f"(c[0]), "+f"(c[1]), "+f"(c[2]), "+f"(c[3])
        : "r"(__float_as_uint(a01.x)), "r"(__float_as_uint(a01.y)),
          "r"(__float_as_uint(a23.x)), "r"(__float_as_uint(a23.y)),
          "r"(__float_as_uint(b01.x)), "r"(__float_as_uint(b01.y)));
}

// ---------------- tensor-core tf32 GEMM (round-4 proven config) ----------------
// 256 thr, CTA tile 128x128, warp tile 32x64, BK=16, double buffer, 1 bar/K-step.
// C[m,n] = sum_k Asel[m,k] * (BT ? B[n,k] : B[k,n]) + bias
// SPLITK: A = A1 (k<ksplit) else A2 (k-ksplit). EPI 1: highway sigmoid blend.
// RND: apply tf32-rna rounding while staging to SMEM (for raw operands).
// ADJ: adjacency mode — blockIdx.z encodes (half, batch); rounds output.
template<bool BT, bool GUARD, int EPI, bool SPLITK, bool RND, bool ADJ>
__global__ __launch_bounds__(256, 2)
void tc_gemm(const float* __restrict__ A1, const float* __restrict__ A2,
             long sA, int lda, int ksplit,
             const float* __restrict__ B1, const float* __restrict__ B2, int nsB,
             long sB, int ldb,
             const float* __restrict__ bias1, const float* __restrict__ bias2, int nsb,
             float* __restrict__ C, long sC, int ldc,
             int M, int N, int K)
{
    __shared__ float2 As2[2][16][68];
    __shared__ float2 Bs2[2][8][132];

    const long zsel = ADJ ? (long)(blockIdx.z & 1023) : (long)blockIdx.z;
    const int  half_adj = ADJ ? (int)(blockIdx.z >> 10) : 0;

    A1 += zsel * sA + (ADJ ? half_adj * NN : 0);
    C  += zsel * sC + (ADJ ? half_adj * HH : 0);
    const float* biasp = (ADJ && half_adj) ? bias2 : bias1;

    const int m0 = blockIdx.y * 128, n0 = blockIdx.x * 128;
    const int tid = threadIdx.x;
    const int lane = tid & 31, warp = tid >> 5;
    const int wm = warp >> 1, wn = warp & 1;
    const int g = lane >> 2, tig = lane & 3;

    const int a_row = tid >> 1, a_kg = (tid & 1) << 3;
    const float* pA1 = A1 + (long)(m0 + a_row) * lda + a_kg;
    const float* pA2 = SPLITK ? (A2 + (long)(m0 + a_row) * lda + a_kg) : pA1;
    const int a_idx  = ((a_row >> 4) << 3) + (a_row & 7);
    const int a_half = (a_row >> 3) & 1;

    const float* Bp;
    int b_kg = 0, b_k = 0, b_n8 = 0;
    if (BT) {
        int b_n = tid >> 1; b_kg = (tid & 1) << 3;
        int gn = n0 + b_n;
        const float* Bsel = (gn < nsB) ? (B1 + (long)gn * ldb)
                                       : (B2 + (long)(gn - nsB) * ldb);
        Bp = Bsel + b_kg;
    } else {
        b_k = tid >> 4;
        b_n8 = (tid & 15) << 3;
        Bp = B1 + zsel * sB + (ADJ ? half_adj * HH : 0) + (long)b_k * ldb + n0 + b_n8;
    }

    float acc[2][8][4] = {};
    __align__(16) float va[8];
    __align__(16) float vb[8];
    const int T = (K + 15) >> 4;

    auto ldg = [&](int k0) {
        if (!GUARD) {
            const float* p;
            if (SPLITK) {
                int kk = k0 + a_kg;
                p = (kk < ksplit) ? (pA1 + k0) : (pA2 + (k0 - ksplit));
            } else {
                p = pA1 + k0;
            }
            *reinterpret_cast<float4*>(va)     = *reinterpret_cast<const float4*>(p);
            *reinterpret_cast<float4*>(va + 4) = *reinterpret_cast<const float4*>(p + 4);
        } else {
            bool rok = (m0 + a_row) < M;
            if (rok && (k0 + a_kg + 8) <= K) {
                *reinterpret_cast<float4*>(va)     = *reinterpret_cast<const float4*>(pA1 + k0);
                *reinterpret_cast<float4*>(va + 4) = *reinterpret_cast<const float4*>(pA1 + k0 + 4);
            } else {
                #pragma unroll
                for (int j = 0; j < 8; j++)
                    va[j] = (rok && (k0 + a_kg + j) < K) ? pA1[k0 + j] : 0.f;
            }
        }
        if (BT) {
            *reinterpret_cast<float4*>(vb)     = *reinterpret_cast<const float4*>(Bp + k0);
            *reinterpret_cast<float4*>(vb + 4) = *reinterpret_cast<const float4*>(Bp + k0 + 4);
        } else {
            if ((k0 + b_k) < K) {
                const float* bp = Bp + (long)k0 * ldb;
                *reinterpret_cast<float4*>(vb)     = *reinterpret_cast<const float4*>(bp);
                *reinterpret_cast<float4*>(vb + 4) = *reinterpret_cast<const float4*>(bp + 4);
            } else {
                #pragma unroll
                for (int j = 0; j < 8; j++) vb[j] = 0.f;
            }
        }
    };

    auto sts = [&](int s) {
        #pragma unroll
        for (int j = 0; j < 8; j++) {
            float* d = &As2[s][a_kg + j][a_idx].x;
            d[a_half] = RND ? totf(va[j]) : va[j];
        }
        if (BT) {
            #pragma unroll
            for (int j = 0; j < 8; j++) {
                int k = b_kg + j;
                float* d = &Bs2[s][((k >> 3) << 2) + (k & 3)][tid >> 1].x;
                d[(k >> 2) & 1] = RND ? totf(vb[j]) : vb[j];
            }
        } else {
            int k = b_k;
            float* drow = &Bs2[s][((k >> 3) << 2) + (k & 3)][b_n8].x;
            int h = (k >> 2) & 1;
            #pragma unroll
            for (int j = 0; j < 8; j++) drow[j * 2 + h] = RND ? totf(vb[j]) : vb[j];
        }
    };

    auto comp = [&](int s) {
        #pragma unroll
        for (int ks = 0; ks < 2; ks++) {
            float2 a01[2], a23[2], bb[8];
            #pragma unroll
            for (int mt = 0; mt < 2; mt++) {
                int idx = (wm * 2 + mt) * 8 + g;
                a01[mt] = As2[s][ks * 8 + tig][idx];
                a23[mt] = As2[s][ks * 8 + tig + 4][idx];
            }
            #pragma unroll
            for (int nt = 0; nt < 8; nt++)
                bb[nt] = Bs2[s][ks * 4 + tig][wn * 64 + nt * 8 + g];
            #pragma unroll
            for (int mt = 0; mt < 2; mt++)
                #pragma unroll
                for (int nt = 0; nt < 8; nt++)
                    mma8(acc[mt][nt], a01[mt], a23[mt], bb[nt]);
        }
    };

    ldg(0); sts(0); __syncthreads();
    for (int t = 0; t < T; t++) {
        if (t + 1 < T) ldg((t + 1) << 4);
        comp(t & 1);
        if (t + 1 < T) { sts((t + 1) & 1); __syncthreads(); }
    }

    // ---------------- epilogue ----------------
    #pragma unroll
    for (int mt = 0; mt < 2; mt++) {
        int mrow = m0 + wm * 32 + mt * 16 + g;
        #pragma unroll
        for (int half = 0; half < 2; half++) {
            int m = mrow + half * 8;
            if (GUARD && m >= M) continue;
            #pragma unroll
            for (int nt = 0; nt < 8; nt++) {
                int n = n0 + wn * 64 + nt * 8 + tig * 2;
                float bv0, bv1;
                if (ADJ) {
                    bv0 = biasp[n]; bv1 = biasp[n + 1];
                } else {
                    bv0 = (n     < nsb) ? bias1[n]     : bias2[n - nsb];
                    bv1 = (n + 1 < nsb) ? bias1[n + 1] : bias2[n + 1 - nsb];
                }
                float v0 = acc[mt][nt][half * 2 + 0] + bv0;
                float v1 = acc[mt][nt][half * 2 + 1] + bv1;
                float2* cp = reinterpret_cast<float2*>(C + (long)m * ldc + n);
                if (EPI == 1) {
                    float2 hv = *reinterpret_cast<const float2*>(A1 + (long)m * lda + n);
                    float2 dv = *reinterpret_cast<const float2*>(A2 + (long)m * lda + n);
                    float a0 = sigm(v0), a1 = sigm(v1);
                    *cp = make_float2(a0 * hv.x + (1.f - a0) * dv.x,
                                      a1 * hv.y + (1.f - a1) * dv.y);
                } else if (ADJ) {
                    *cp = make_float2(totf(v0), totf(v1));
                } else {
                    *cp = make_float2(v0, v1);
                }
            }
        }
    }
}

// ---------------- fused weight rounding (single launch) ----------------
__global__ void wround_k(const float4* w_ih, const float4* w_hh,
                         const float4* W_ein, const float4* W_eout, const float4* W_hn,
                         float4* wih, float4* whh, float4* wein, float4* weout, float4* whn)
{
    const int S0 = 24576, S1 = S0 + 12288, S2 = S1 + 4096, S3 = S2 + 4096, S4 = S3 + 8192;
    for (int i = blockIdx.x * blockDim.x + threadIdx.x; i < S4; i += gridDim.x * blockDim.x) {
        const float4* s; float4* d; int j;
        if      (i < S0) { s = w_ih;   d = wih;   j = i; }
        else if (i < S1) { s = w_hh;   d = whh;   j = i - S0; }
        else if (i < S2) { s = W_ein;  d = wein;  j = i - S1; }
        else if (i < S3) { s = W_eout; d = weout; j = i - S2; }
        else             { s = W_hn;   d = whn;   j = i - S3; }
        float4 v = s[j];
        d[j] = make_float4(totf(v.x), totf(v.y), totf(v.z), totf(v.w));
    }
}

// ---------------- fused gather + ave-pool (rounded h0, initial star) -------
__global__ void gather_pool_k(const int* __restrict__ inputs,
                              const float* __restrict__ emb,
                              const int* __restrict__ gm,
                              float* __restrict__ h0,
                              float* __restrict__ star)
{
    int b = blockIdx.x, t = threadIdx.x;
    const int* ib = inputs + b * NN;
    const int* gb = gm + b * NN;
    float* hb = h0 + (long)b * NN * HH;
    float s = 0.f, c = 0.f;
    for (int i = 0; i < NN; i++) {
        float v = totf(emb[(long)ib[i] * HH + t]);
        hb[(long)i * HH + t] = v;
        float g = (float)gb[i];
        s += g * v;
        c += g;
    }
    star[(long)b * HH + t] = s / c;
}

// ---------- fused GRU + star blend + attention pooling ----------
// writes hid (tf32-rounded) and final star straight into star_out.
__global__ void star_gru_k(const float* __restrict__ gi, const float* __restrict__ gh,
                           const float* __restrict__ h0, const int* __restrict__ gm,
                           const float* __restrict__ star_in,
                           float* __restrict__ hid, float* __restrict__ star_out)
{
    const float inv_sqrt_h = 0.0883883476483184f;  // 1/sqrt(128)
    int b = blockIdx.x;
    int t = threadIdx.x;
    int lane = t & 31, warp = t >> 5;

    __shared__ float st[HH];
    __shared__ float w[NN];
    __shared__ float red[HH];

    st[t] = star_in[(long)b * HH + t];
    __syncthreads();

    float ssp = 0.f;
    #pragma unroll
    for (int u = 0; u < 4; u++) { float v = st[lane + 32 * u]; ssp += v * v; }
    #pragma unroll
    for (int off = 16; off > 0; off >>= 1) ssp += __shfl_xor_sync(0xffffffffu, ssp, off);
    float ss = ssp;

    float* hb = hid + (long)b * NN * HH;

    for (int i = warp; i < NN; i += 4) {
        long row = (long)b * NN + i;
        const float* gir = gi + row * (3 * HH);
        const float* ghr = gh + row * (3 * HH);
        const float* h0r = h0 + row * HH;
        float hv[4];
        float d = 0.f;
        #pragma unroll
        for (int u = 0; u < 4; u++) {
            int c = lane + 32 * u;
            float r  = sigm(gir[c] + ghr[c]);
            float ig = sigm(gir[c + HH] + ghr[c + HH]);
            float ng = tanhf(gir[c + 2 * HH] + r * ghr[c + 2 * HH]);
            float h  = h0r[c];
            hv[u] = ng + ig * (h - ng);
            d += hv[u] * st[c];
        }
        #pragma unroll
        for (int off = 16; off > 0; off >>= 1) d += __shfl_xor_sync(0xffffffffu, d, off);
        float alpha = sigm(d * inv_sqrt_h);
        float* hr = hb + (long)i * HH;
        #pragma unroll
        for (int u = 0; u < 4; u++) {
            int c = lane + 32 * u;
            hr[c] = totf((1.f - alpha) * hv[u] + alpha * st[c]);
        }
        float d2 = (1.f - alpha) * d + alpha * ss;
        if (lane == 0) w[i] = expf(d2) * (float)gm[b * NN + i];
    }
    __syncthreads();

    red[t] = (t < NN) ? w[t] : 0.f;
    __syncthreads();
    for (int s = 64; s > 0; s >>= 1) {
        if (t < s) red[t] += red[t + s];
        __syncthreads();
    }
    float S = red[0] + 1e-24f;

    float acc = 0.f;
    for (int i = 0; i < NN; i++) acc += w[i] * hb[(long)i * HH + t];
    star_out[(long)b * HH + t] = acc / S;
}

// ---------------- launch ----------------
extern "C" void kernel_launch(void* const* d_in, const int* in_sizes, int n_in,
                              void* d_out, int out_size)
{
    const int*   inputs = (const int*)d_in[0];
    const float* A      = (const float*)d_in[1];
    const int*   gm     = (const int*)d_in[2];
    const float* emb    = (const float*)d_in[3];
    const float* w_ih   = (const float*)d_in[4];
    const float* w_hh   = (const float*)d_in[5];
    const float* b_ih   = (const float*)d_in[6];
    const float* b_hh   = (const float*)d_in[7];
    const float* b_iah  = (const float*)d_in[8];
    const float* b_oah  = (const float*)d_in[9];
    const float* W_ein  = (const float*)d_in[10];
    const float* b_ein  = (const float*)d_in[11];
    const float* W_eout = (const float*)d_in[12];
    const float* b_eout = (const float*)d_in[13];
    const float* W_hn   = (const float*)d_in[14];
    const float* b_hn   = (const float*)d_in[15];
    float* out = (float*)d_out;

    float *h0, *e, *inp, *gi, *gh, *hid, *star;
    float *wih, *whh, *wein, *weout, *whn;
    cudaGetSymbolAddress((void**)&h0,    g_h0);
    cudaGetSymbolAddress((void**)&e,     g_e);
    cudaGetSymbolAddress((void**)&inp,   g_inp);
    cudaGetSymbolAddress((void**)&gi,    g_gi);
    cudaGetSymbolAddress((void**)&gh,    g_gh);
    cudaGetSymbolAddress((void**)&hid,   g_hid);
    cudaGetSymbolAddress((void**)&star,  g_star);
    cudaGetSymbolAddress((void**)&wih,   g_wih);
    cudaGetSymbolAddress((void**)&whh,   g_whh);
    cudaGetSymbolAddress((void**)&wein,  g_wein);
    cudaGetSymbolAddress((void**)&weout, g_weout);
    cudaGetSymbolAddress((void**)&whn,   g_whn);

    const long totBNH = (long)MTOT * HH;
    const int BIG = 1 << 30;

    // 0) round all weights (tf32-rna), one launch
    wround_k<<<208, 256>>>((const float4*)w_ih, (const float4*)w_hh,
                           (const float4*)W_ein, (const float4*)W_eout, (const float4*)W_hn,
                           (float4*)wih, (float4*)whh, (float4*)wein, (float4*)weout, (float4*)whn);

    // 1) fused gather (rounded) + initial star
    gather_pool_k<<<BSZ, HH>>>(inputs, emb, gm, h0, star);

    // 2) e = [h0 @ W_ein^T + b_ein | h0 @ W_eout^T + b_eout]  (pre-rounded operands)
    tc_gemm<true, false, 0, false, false, false><<<dim3(2, MTOT / 128), 256>>>(
        h0, h0, 0, HH, 0,
        wein, weout, HH, 0, HH,
        b_ein, b_eout, HH,
        e, 0, 2 * HH,
        MTOT, 2 * HH, HH);

    // 3) both adjacency GEMMs in one launch (z: 0..1023 = in-half, 1024..2047 = out-half)
    tc_gemm<false, true, 0, false, true, true><<<dim3(1, 1, 2 * BSZ), 256>>>(
        A, A, (long)NN * 2 * NN, 2 * NN, 0,
        e, e, BIG, (long)NN * 2 * HH, 2 * HH,
        b_iah, b_oah, BIG,
        inp, (long)NN * 2 * HH, 2 * HH,
        NN, HH, NN);

    // 4) gi = inp @ w_ih^T + b_ih ; gh = h0 @ w_hh^T + b_hh (pre-rounded operands)
    tc_gemm<true, false, 0, false, false, false><<<dim3(3, MTOT / 128), 256>>>(
        inp, inp, 0, 2 * HH, 0,
        wih, wih, BIG, 0, 2 * HH,
        b_ih, b_ih, BIG,
        gi, 0, 3 * HH,
        MTOT, 3 * HH, 2 * HH);
    tc_gemm<true, false, 0, false, false, false><<<dim3(3, MTOT / 128), 256>>>(
        h0, h0, 0, HH, 0,
        whh, whh, BIG, 0, HH,
        b_hh, b_hh, BIG,
        gh, 0, 3 * HH,
        MTOT, 3 * HH, HH);

    // 5+6) fused GRU + star blend + attention pooling (writes hid, star -> out tail)
    star_gru_k<<<BSZ, HH>>>(gi, gh, h0, gm, star, hid, out + totBNH);

    // 7+8) highway fused: [h0|hid] @ W_hn^T + b_hn (split-K), sigmoid blend -> out
    tc_gemm<true, false, 1, true, false, false><<<dim3(1, MTOT / 128), 256>>>(
        h0, hid, 0, HH, HH,
        whn, whn, BIG, 0, 2 * HH,
        b_hn, b_hn, BIG,
        out, 0, HH,
        MTOT, HH, 2 * HH);
}

// round 11
// speedup vs baseline: 1.2006x; 1.0903x over previous
#include <cuda_runtime.h>
#include <math.h>
#include <stdint.h>

#define BSZ 1024
#define NN  100
#define HH  128
#define MTOT (BSZ * NN)   // 102400

// ---------------- scratch (no allocs allowed) ----------------
__device__ float g_h0[(size_t)MTOT * HH];
__device__ float g_e[(size_t)MTOT * 2 * HH];
__device__ float g_inp[(size_t)MTOT * 2 * HH];
__device__ float g_gi[(size_t)MTOT * 3 * HH];
__device__ float g_gh[(size_t)MTOT * 3 * HH];
__device__ float g_hid[(size_t)MTOT * HH];
__device__ float g_star[(size_t)BSZ * HH];
// tf32-rounded weight copies
__device__ float g_wih[3 * HH * 2 * HH];
__device__ float g_whh[3 * HH * HH];
__device__ float g_wein[HH * HH];
__device__ float g_weout[HH * HH];
__device__ float g_whn[HH * 2 * HH];

// ---------------- helpers ----------------
__device__ __forceinline__ float totf(float x) {
    uint32_t u; asm("cvt.rna.tf32.f32 %0, %1;" : "=r"(u) : "f"(x));
    return __uint_as_float(u);
}
__device__ __forceinline__ float sigm(float x) { return 1.f / (1.f + expf(-x)); }

__device__ __forceinline__ void mma8(float c[4], float2 a01, float2 a23, float2 b01) {
    asm volatile(
        "mma.sync.aligned.m16n8k8.row.col.f32.tf32.tf32.f32 "
        "{%0,%1,%2,%3},{%4,%5,%6,%7},{%8,%9},{%0,%1,%2,%3};"
        : "+f"(c[0]), "+f"(c[1]), "+f"(c[2]), "+f"(c[3])
        : "r"(__float_as_uint(a01.x)), "r"(__float_as_uint(a01.y)),
          "r"(__float_as_uint(a23.x)), "r"(__float_as_uint(a23.y)),
          "r"(__float_as_uint(b01.x)), "r"(__float_as_uint(b01.y)));
}

// ---------------- tensor-core tf32 GEMM ----------------
// 256 thr, CTA tile 128x128, warp tile 32x64, BK=16, double buffer, 1 bar/K-step.
// float4-quad SMEM layout: one LDS.128 = one full A fragment / two B fragments.
// A quad (srow=((k>>3)<<2)+(k&3), idx=((m>>4)<<3)+(m&7)):
//   {A[m][k], A[m+8][k], A[m][k+4], A[m+8][k+4]}   comp = ((k>>2)&1)*2 + ((m>>3)&1)
// B quad (same srow, idx q = p ^ ((p>>3)&7), p=((n>>4)<<3)+(n&7)):
//   {B[n][k], B[n][k+4], B[n+8][k], B[n+8][k+4]}   comp = ((n>>3)&1)*2 + ((k>>2)&1)
template<bool BT, bool GUARD, int EPI, bool SPLITK, bool RND, bool ADJ>
__global__ __launch_bounds__(256, 2)
void tc_gemm(const float* __restrict__ A1, const float* __restrict__ A2,
             long sA, int lda, int ksplit,
             const float* __restrict__ B1, const float* __restrict__ B2, int nsB,
             long sB, int ldb,
             const float* __restrict__ bias1, const float* __restrict__ bias2, int nsb,
             float* __restrict__ C, long sC, int ldc,
             int M, int N, int K)
{
    __shared__ float4 As4[2][8][66];
    __shared__ float4 Bs4[2][8][66];

    const long zsel = ADJ ? (long)(blockIdx.z & 1023) : (long)blockIdx.z;
    const int  half_adj = ADJ ? (int)(blockIdx.z >> 10) : 0;

    A1 += zsel * sA + (ADJ ? half_adj * NN : 0);
    C  += zsel * sC + (ADJ ? half_adj * HH : 0);
    const float* biasp = (ADJ && half_adj) ? bias2 : bias1;

    const int m0 = blockIdx.y * 128, n0 = blockIdx.x * 128;
    const int tid = threadIdx.x;
    const int lane = tid & 31, warp = tid >> 5;
    const int wm = warp >> 1, wn = warp & 1;
    const int g = lane >> 2, tig = lane & 3;

    const int a_row = tid >> 1, a_kg = (tid & 1) << 3;
    const float* pA1 = A1 + (long)(m0 + a_row) * lda + a_kg;
    const float* pA2 = SPLITK ? (A2 + (long)(m0 + a_row) * lda + a_kg) : pA1;
    const int a_idx  = ((a_row >> 4) << 3) + (a_row & 7);
    const int a_half = (a_row >> 3) & 1;

    const float* Bp;
    int b_kg = 0, b_k = 0, b_n8 = 0;
    int bq = 0, bsel = 0;
    if (BT) {
        int b_n = tid >> 1; b_kg = (tid & 1) << 3;
        int gn = n0 + b_n;
        const float* Bsel = (gn < nsB) ? (B1 + (long)gn * ldb)
                                       : (B2 + (long)(gn - nsB) * ldb);
        Bp = Bsel + b_kg;
        int p = ((b_n >> 4) << 3) + (b_n & 7);
        bq = p ^ ((p >> 3) & 7);
        bsel = (b_n >> 3) & 1;
    } else {
        b_k = tid >> 4;
        b_n8 = (tid & 15) << 3;
        Bp = B1 + zsel * sB + (ADJ ? half_adj * HH : 0) + (long)b_k * ldb + n0 + b_n8;
        bsel = (b_n8 >> 3) & 1;
    }

    float acc[2][8][4] = {};
    __align__(16) float va[8];
    __align__(16) float vb[8];
    const int T = (K + 15) >> 4;

    auto ldg = [&](int k0) {
        if (!GUARD) {
            const float* p;
            if (SPLITK) {
                int kk = k0 + a_kg;
                p = (kk < ksplit) ? (pA1 + k0) : (pA2 + (k0 - ksplit));
            } else {
                p = pA1 + k0;
            }
            *reinterpret_cast<float4*>(va)     = *reinterpret_cast<const float4*>(p);
            *reinterpret_cast<float4*>(va + 4) = *reinterpret_cast<const float4*>(p + 4);
        } else {
            bool rok = (m0 + a_row) < M;
            if (rok && (k0 + a_kg + 8) <= K) {
                *reinterpret_cast<float4*>(va)     = *reinterpret_cast<const float4*>(pA1 + k0);
                *reinterpret_cast<float4*>(va + 4) = *reinterpret_cast<const float4*>(pA1 + k0 + 4);
            } else {
                #pragma unroll
                for (int j = 0; j < 8; j++)
                    va[j] = (rok && (k0 + a_kg + j) < K) ? pA1[k0 + j] : 0.f;
            }
        }
        if (BT) {
            *reinterpret_cast<float4*>(vb)     = *reinterpret_cast<const float4*>(Bp + k0);
            *reinterpret_cast<float4*>(vb + 4) = *reinterpret_cast<const float4*>(Bp + k0 + 4);
        } else {
            if ((k0 + b_k) < K) {
                const float* bp = Bp + (long)k0 * ldb;
                *reinterpret_cast<float4*>(vb)     = *reinterpret_cast<const float4*>(bp);
                *reinterpret_cast<float4*>(vb + 4) = *reinterpret_cast<const float4*>(bp + 4);
            } else {
                #pragma unroll
                for (int j = 0; j < 8; j++) vb[j] = 0.f;
            }
        }
    };

    auto sts = [&](int s) {
        #pragma unroll
        for (int j = 0; j < 8; j++) {
            int k = a_kg + j;
            int srow = ((k >> 3) << 2) + (k & 3);
            int comp = (((k >> 2) & 1) << 1) | a_half;
            (&As4[s][srow][a_idx].x)[comp] = RND ? totf(va[j]) : va[j];
        }
        if (BT) {
            #pragma unroll
            for (int j = 0; j < 8; j++) {
                int k = b_kg + j;
                int srow = ((k >> 3) << 2) + (k & 3);
                int comp = (bsel << 1) | ((k >> 2) & 1);
                (&Bs4[s][srow][bq].x)[comp] = RND ? totf(vb[j]) : vb[j];
            }
        } else {
            int srow = ((b_k >> 3) << 2) + (b_k & 3);
            int comp = (bsel << 1) | ((b_k >> 2) & 1);
            int p0 = (b_n8 >> 4) << 3;
            int x  = (p0 >> 3) & 7;
            #pragma unroll
            for (int j = 0; j < 8; j++) {
                // value for n = b_n8 + j goes to swizzled slot p0 + (j ^ x)
                int q = p0 + (j ^ x);
                (&Bs4[s][srow][q].x)[comp] = RND ? totf(vb[j]) : vb[j];
            }
        }
    };

    auto comp = [&](int s) {
        #pragma unroll
        for (int ks = 0; ks < 2; ks++) {
            float4 af[2], bf[4];
            #pragma unroll
            for (int mt = 0; mt < 2; mt++)
                af[mt] = As4[s][ks * 4 + tig][(wm * 2 + mt) * 8 + g];
            #pragma unroll
            for (int np = 0; np < 4; np++) {
                int j = wn * 32 + np * 8 + g;
                bf[np] = Bs4[s][ks * 4 + tig][j ^ ((j >> 3) & 7)];
            }
            #pragma unroll
            for (int mt = 0; mt < 2; mt++)
                #pragma unroll
                for (int np = 0; np < 4; np++) {
                    mma8(acc[mt][2 * np],
                         make_float2(af[mt].x, af[mt].y), make_float2(af[mt].z, af[mt].w),
                         make_float2(bf[np].x, bf[np].y));
                    mma8(acc[mt][2 * np + 1],
                         make_float2(af[mt].x, af[mt].y), make_float2(af[mt].z, af[mt].w),
                         make_float2(bf[np].z, bf[np].w));
                }
        }
    };

    ldg(0); sts(0); __syncthreads();
    for (int t = 0; t < T; t++) {
        if (t + 1 < T) ldg((t + 1) << 4);
        comp(t & 1);
        if (t + 1 < T) { sts((t + 1) & 1); __syncthreads(); }
    }

    // ---------------- epilogue ----------------
    #pragma unroll
    for (int mt = 0; mt < 2; mt++) {
        int mrow = m0 + wm * 32 + mt * 16 + g;
        #pragma unroll
        for (int half = 0; half < 2; half++) {
            int m = mrow + half * 8;
            if (GUARD && m >= M) continue;
            #pragma unroll
            for (int nt = 0; nt < 8; nt++) {
                int n = n0 + wn * 64 + nt * 8 + tig * 2;
                float bv0, bv1;
                if (ADJ) {
                    bv0 = biasp[n]; bv1 = biasp[n + 1];
                } else {
                    bv0 = (n     < nsb) ? bias1[n]     : bias2[n - nsb];
                    bv1 = (n + 1 < nsb) ? bias1[n + 1] : bias2[n + 1 - nsb];
                }
                float v0 = acc[mt][nt][half * 2 + 0] + bv0;
                float v1 = acc[mt][nt][half * 2 + 1] + bv1;
                float2* cp = reinterpret_cast<float2*>(C + (long)m * ldc + n);
                if (EPI == 1) {
                    float2 hv = *reinterpret_cast<const float2*>(A1 + (long)m * lda + n);
                    float2 dv = *reinterpret_cast<const float2*>(A2 + (long)m * lda + n);
                    float a0 = sigm(v0), a1 = sigm(v1);
                    *cp = make_float2(a0 * hv.x + (1.f - a0) * dv.x,
                                      a1 * hv.y + (1.f - a1) * dv.y);
                } else if (ADJ) {
                    *cp = make_float2(totf(v0), totf(v1));
                } else {
                    *cp = make_float2(v0, v1);
                }
            }
        }
    }
}

// ---------------- fused weight rounding (single launch) ----------------
__global__ void wround_k(const float4* w_ih, const float4* w_hh,
                         const float4* W_ein, const float4* W_eout, const float4* W_hn,
                         float4* wih, float4* whh, float4* wein, float4* weout, float4* whn)
{
    const int S0 = 24576, S1 = S0 + 12288, S2 = S1 + 4096, S3 = S2 + 4096, S4 = S3 + 8192;
    for (int i = blockIdx.x * blockDim.x + threadIdx.x; i < S4; i += gridDim.x * blockDim.x) {
        const float4* s; float4* d; int j;
        if      (i < S0) { s = w_ih;   d = wih;   j = i; }
        else if (i < S1) { s = w_hh;   d = whh;   j = i - S0; }
        else if (i < S2) { s = W_ein;  d = wein;  j = i - S1; }
        else if (i < S3) { s = W_eout; d = weout; j = i - S2; }
        else             { s = W_hn;   d = whn;   j = i - S3; }
        float4 v = s[j];
        d[j] = make_float4(totf(v.x), totf(v.y), totf(v.z), totf(v.w));
    }
}

// ---------------- wide gather (rounded) ----------------
__global__ void gather_k(const int* __restrict__ inputs,
                         const float4* __restrict__ emb4,
                         float4* __restrict__ h04, long total4)
{
    long i = (long)blockIdx.x * blockDim.x + threadIdx.x;
    if (i >= total4) return;
    long m = i >> 5;
    int  t = (int)(i & 31);
    float4 v = emb4[(long)inputs[m] * 32 + t];
    h04[i] = make_float4(totf(v.x), totf(v.y), totf(v.z), totf(v.w));
}

__global__ void pool_k(const float* __restrict__ h0,
                       const int* __restrict__ gm,
                       float* __restrict__ star)
{
    int b = blockIdx.x, t = threadIdx.x;
    float s = 0.f, c = 0.f;
    const float* hb = h0 + (long)b * NN * HH;
    const int* gb = gm + b * NN;
    for (int i = 0; i < NN; i++) {
        float gmask = (float)gb[i];
        s += gmask * hb[(long)i * HH + t];
        c += gmask;
    }
    star[b * HH + t] = s / c;
}

// ---------------- wide GRU elementwise ----------------
__global__ void gru_k(const float* __restrict__ gi, const float* __restrict__ gh,
                      const float* __restrict__ h0, float* __restrict__ hout,
                      long total)
{
    long i = (long)blockIdx.x * blockDim.x + threadIdx.x;
    if (i >= total) return;
    long m = i >> 7;
    int  j = (int)(i & 127);
    long base = m * (3 * HH);
    float ir = gi[base + j],         hr = gh[base + j];
    float ii = gi[base + HH + j],    hi = gh[base + HH + j];
    float in_ = gi[base + 2*HH + j], hn = gh[base + 2*HH + j];
    float r  = sigm(ir + hr);
    float ig = sigm(ii + hi);
    float ng = tanhf(in_ + r * hn);
    float h  = h0[i];
    hout[i] = ng + ig * (h - ng);
}

// ---------------- star blend + attention pooling ----------------
// blends hidden in place (tf32-rounded), writes final star to star_out
__global__ void star_k(float* __restrict__ hidden,
                       const int* __restrict__ gm,
                       const float* __restrict__ star_in,
                       float* __restrict__ star_out)
{
    const float inv_sqrt_h = 0.0883883476483184f;  // 1/sqrt(128)
    int b = blockIdx.x;
    int t = threadIdx.x;
    int lane = t & 31, warp = t >> 5;

    __shared__ float st[HH];
    __shared__ float w[NN];
    __shared__ float red[HH];

    st[t] = star_in[(long)b * HH + t];
    __syncthreads();

    float ssp = 0.f;
    #pragma unroll
    for (int u = 0; u < 4; u++) { float v = st[lane + 32 * u]; ssp += v * v; }
    #pragma unroll
    for (int off = 16; off > 0; off >>= 1) ssp += __shfl_xor_sync(0xffffffffu, ssp, off);
    float ss = ssp;

    float* hb = hidden + (long)b * NN * HH;

    for (int i = warp; i < NN; i += 4) {
        float* hr = hb + (long)i * HH;
        float d = 0.f;
        #pragma unroll
        for (int u = 0; u < 4; u++) d += hr[lane + 32 * u] * st[lane + 32 * u];
        #pragma unroll
        for (int off = 16; off > 0; off >>= 1) d += __shfl_xor_sync(0xffffffffu, d, off);
        float alpha = sigm(d * inv_sqrt_h);
        #pragma unroll
        for (int u = 0; u < 4; u++) {
            int c = lane + 32 * u;
            hr[c] = totf((1.f - alpha) * hr[c] + alpha * st[c]);
        }
        float d2 = (1.f - alpha) * d + alpha * ss;
        if (lane == 0) w[i] = expf(d2) * (float)gm[b * NN + i];
    }
    __syncthreads();

    red[t] = (t < NN) ? w[t] : 0.f;
    __syncthreads();
    for (int s = 64; s > 0; s >>= 1) {
        if (t < s) red[t] += red[t + s];
        __syncthreads();
    }
    float S = red[0] + 1e-24f;

    float acc = 0.f;
    for (int i = 0; i < NN; i++) acc += w[i] * hb[(long)i * HH + t];
    star_out[(long)b * HH + t] = acc / S;
}

// ---------------- launch ----------------
extern "C" void kernel_launch(void* const* d_in, const int* in_sizes, int n_in,
                              void* d_out, int out_size)
{
    const int*   inputs = (const int*)d_in[0];
    const float* A      = (const float*)d_in[1];
    const int*   gm     = (const int*)d_in[2];
    const float* emb    = (const float*)d_in[3];
    const float* w_ih   = (const float*)d_in[4];
    const float* w_hh   = (const float*)d_in[5];
    const float* b_ih   = (const float*)d_in[6];
    const float* b_hh   = (const float*)d_in[7];
    const float* b_iah  = (const float*)d_in[8];
    const float* b_oah  = (const float*)d_in[9];
    const float* W_ein  = (const float*)d_in[10];
    const float* b_ein  = (const float*)d_in[11];
    const float* W_eout = (const float*)d_in[12];
    const float* b_eout = (const float*)d_in[13];
    const float* W_hn   = (const float*)d_in[14];
    const float* b_hn   = (const float*)d_in[15];
    float* out = (float*)d_out;

    float *h0, *e, *inp, *gi, *gh, *hid, *star;
    float *wih, *whh, *wein, *weout, *whn;
    cudaGetSymbolAddress((void**)&h0,    g_h0);
    cudaGetSymbolAddress((void**)&e,     g_e);
    cudaGetSymbolAddress((void**)&inp,   g_inp);
    cudaGetSymbolAddress((void**)&gi,    g_gi);
    cudaGetSymbolAddress((void**)&gh,    g_gh);
    cudaGetSymbolAddress((void**)&hid,   g_hid);
    cudaGetSymbolAddress((void**)&star,  g_star);
    cudaGetSymbolAddress((void**)&wih,   g_wih);
    cudaGetSymbolAddress((void**)&whh,   g_whh);
    cudaGetSymbolAddress((void**)&wein,  g_wein);
    cudaGetSymbolAddress((void**)&weout, g_weout);
    cudaGetSymbolAddress((void**)&whn,   g_whn);

    const long totBNH = (long)MTOT * HH;
    const int BIG = 1 << 30;

    // 0) round all weights (tf32-rna), one launch
    wround_k<<<208, 256>>>((const float4*)w_ih, (const float4*)w_hh,
                           (const float4*)W_ein, (const float4*)W_eout, (const float4*)W_hn,
                           (float4*)wih, (float4*)whh, (float4*)wein, (float4*)weout, (float4*)whn);

    // 1) wide gather (rounded) + initial star
    gather_k<<<(unsigned)((totBNH / 4 + 255) / 256), 256>>>(
        inputs, (const float4*)emb, (float4*)h0, totBNH / 4);
    pool_k<<<BSZ, HH>>>(h0, gm, star);

    // 2) e = [h0 @ W_ein^T + b_ein | h0 @ W_eout^T + b_eout]  (pre-rounded operands)
    tc_gemm<true, false, 0, false, false, false><<<dim3(2, MTOT / 128), 256>>>(
        h0, h0, 0, HH, 0,
        wein, weout, HH, 0, HH,
        b_ein, b_eout, HH,
        e, 0, 2 * HH,
        MTOT, 2 * HH, HH);

    // 3) both adjacency GEMMs in one launch (z: 0..1023 in-half, 1024..2047 out-half)
    tc_gemm<false, true, 0, false, true, true><<<dim3(1, 1, 2 * BSZ), 256>>>(
        A, A, (long)NN * 2 * NN, 2 * NN, 0,
        e, e, BIG, (long)NN * 2 * HH, 2 * HH,
        b_iah, b_oah, BIG,
        inp, (long)NN * 2 * HH, 2 * HH,
        NN, HH, NN);

    // 4) gi = inp @ w_ih^T + b_ih ; gh = h0 @ w_hh^T + b_hh (pre-rounded operands)
    tc_gemm<true, false, 0, false, false, false><<<dim3(3, MTOT / 128), 256>>>(
        inp, inp, 0, 2 * HH, 0,
        wih, wih, BIG, 0, 2 * HH,
        b_ih, b_ih, BIG,
        gi, 0, 3 * HH,
        MTOT, 3 * HH, 2 * HH);
    tc_gemm<true, false, 0, false, false, false><<<dim3(3, MTOT / 128), 256>>>(
        h0, h0, 0, HH, 0,
        whh, whh, BIG, 0, HH,
        b_hh, b_hh, BIG,
        gh, 0, 3 * HH,
        MTOT, 3 * HH, HH);

    // 5) wide GRU elementwise -> hid
    gru_k<<<(unsigned)((totBNH + 255) / 256), 256>>>(gi, gh, h0, hid, totBNH);

    // 6) star blend + attention pooling (rounds hid, final star -> out tail)
    star_k<<<BSZ, HH>>>(hid, gm, star, out + totBNH);

    // 7+8) highway fused: [h0|hid] @ W_hn^T + b_hn (split-K), sigmoid blend -> out
    tc_gemm<true, false, 1, true, false, false><<<dim3(1, MTOT / 128), 256>>>(
        h0, hid, 0, HH, HH,
        whn, whn, BIG, 0, 2 * HH,
        b_hn, b_hn, BIG,
        out, 0, HH,
        MTOT, HH, 2 * HH);
}